// round 2
// baseline (speedup 1.0000x reference)
#include <cuda_runtime.h>

// DispCorrM: out[b,d,h,w] = (1/C) * sum_c L[b,c,h,w] * R[b,c,h,w-d]   (0 if w<d)
// x: (B, 2C, H, W) fp32, L = x[:, :C], R = x[:, C:]
// Fixed shapes: B=4, C=32, H=256, W=512, D=64.

#define BB 4
#define CC 32
#define HH 256
#define WW 512
#define DD 64

#define TW 128           // w-tile per block
#define RW (64 + TW)     // R tile width incl. 64-col left halo/zero-pad
#define ND 16            // d's per thread (per warp-group)
#define NW 4             // w's per thread

typedef unsigned long long ull;

__device__ __forceinline__ ull pack2(float lo, float hi) {
    ull v;
    asm("mov.b64 %0, {%1, %2};" : "=l"(v) : "f"(lo), "f"(hi));
    return v;
}
__device__ __forceinline__ void fma2(ull& acc, ull a, ull b) {
    // packed (a.lo*b.lo + acc.lo, a.hi*b.hi + acc.hi)
    asm("fma.rn.f32x2 %0, %1, %2, %0;" : "+l"(acc) : "l"(a), "l"(b));
}
__device__ __forceinline__ void unpack2(ull v, float& lo, float& hi) {
    asm("mov.b64 {%0, %1}, %2;" : "=f"(lo), "=f"(hi) : "l"(v));
}

__global__ __launch_bounds__(128)
void disp_corr_kernel(const float* __restrict__ x, float* __restrict__ out) {
    __shared__ float Lsh[CC][TW];   // 16 KB
    __shared__ float Rsh[CC][RW];   // 24 KB

    const int tile = blockIdx.x;            // 0..3
    const int h    = blockIdx.y;            // 0..255
    const int b    = blockIdx.z;            // 0..3
    const int tile_start = tile * TW;
    const int tid = threadIdx.x;

    const size_t chan_stride = (size_t)HH * WW;

    // ---- Load L tile: channels 0..31, w in [tile_start, tile_start+TW) ----
    {
        const float* Lg = x + ((size_t)(b * 2 * CC) * HH + h) * WW + tile_start;
        #pragma unroll
        for (int k = 0; k < (CC * TW / 4) / 128; k++) {
            int idx = k * 128 + tid;
            int c  = idx / (TW / 4);
            int w4 = idx % (TW / 4);
            float4 v = *(const float4*)(Lg + (size_t)c * chan_stride + 4 * w4);
            *(float4*)&Lsh[c][4 * w4] = v;
        }
    }

    // ---- Load R tile: channels 32..63, local j maps to w = tile_start + j - 64 ----
    {
        const float* Rg = x + ((size_t)(b * 2 * CC + CC) * HH + h) * WW;
        for (int idx = tid; idx < CC * (RW / 4); idx += 128) {
            int c  = idx / (RW / 4);
            int j4 = idx % (RW / 4);
            int wg = tile_start + 4 * j4 - 64;
            float4 v;
            if (wg >= 0) {
                v = *(const float4*)(Rg + (size_t)c * chan_stride + wg);
            } else {
                v = make_float4(0.f, 0.f, 0.f, 0.f);
            }
            *(float4*)&Rsh[c][4 * j4] = v;
        }
    }

    __syncthreads();

    const int lane = tid & 31;
    const int warp = tid >> 5;            // 0..3
    const int w0 = lane * 4;              // stride-16B across lanes: conflict-free LDS.128
    const int d0 = warp * ND;             // 0,16,32,48

    // Packed f32x2 accumulators: acc01[dd] = (acc_w0, acc_w1), acc23[dd] = (acc_w2, acc_w3)
    ull acc01[ND], acc23[ND];
    #pragma unroll
    for (int i = 0; i < ND; i++) { acc01[i] = 0ULL; acc23[i] = 0ULL; }

    // R shared index for (w0+i, d0+dd) is 64 + w0 + i - d0 - dd = rbase + 16 - dd + i
    const int rbase = 64 + w0 - d0 - 16;   // multiple of 4

    #pragma unroll 2
    for (int c = 0; c < CC; c++) {
        float4 Lv = *(const float4*)&Lsh[c][w0];
        ull La = pack2(Lv.x, Lv.y);
        ull Lb = pack2(Lv.z, Lv.w);

        float r[20];
        #pragma unroll
        for (int q = 0; q < 5; q++)
            *(float4*)&r[4 * q] = *(const float4*)&Rsh[c][rbase + 4 * q];

        #pragma unroll
        for (int dd = 0; dd < ND; dd++) {
            fma2(acc01[dd], La, pack2(r[16 - dd + 0], r[16 - dd + 1]));
            fma2(acc23[dd], Lb, pack2(r[16 - dd + 2], r[16 - dd + 3]));
        }
    }

    // ---- Epilogue: scale by 1/C and store (float4, contiguous per warp) ----
    const float inv_c = 1.0f / (float)CC;
    float* og = out + (((size_t)b * DD + d0) * HH + h) * WW + tile_start + w0;
    #pragma unroll
    for (int dd = 0; dd < ND; dd++) {
        float a0, a1, a2, a3;
        unpack2(acc01[dd], a0, a1);
        unpack2(acc23[dd], a2, a3);
        float4 v = make_float4(a0 * inv_c, a1 * inv_c, a2 * inv_c, a3 * inv_c);
        *(float4*)(og + (size_t)dd * chan_stride) = v;
    }
}

extern "C" void kernel_launch(void* const* d_in, const int* in_sizes, int n_in,
                              void* d_out, int out_size) {
    const float* x = (const float*)d_in[0];
    float* out = (float*)d_out;
    dim3 grid(WW / TW, HH, BB);   // (4, 256, 4) = 4096 blocks
    disp_corr_kernel<<<grid, 128>>>(x, out);
}

// round 3
// speedup vs baseline: 1.7344x; 1.7344x over previous
#include <cuda_runtime.h>

// DispCorrM: out[b,d,h,w] = (1/C) * sum_c L[b,c,h,w] * R[b,c,h,w-d]   (0 if w<d)
// x: (B, 2C, H, W) fp32, L = x[:, :C], R = x[:, C:]
// Fixed shapes: B=4, C=32, H=256, W=512, D=64.

#define BB 4
#define CC 32
#define HH 256
#define WW 512
#define DD 64

#define TW 128           // w-tile per block
#define RW (64 + TW)     // R tile width incl. 64-col left halo/zero-pad
#define ND 16            // d's per thread (per warp)
#define NW 4             // w's per thread
#define CH 16            // channels per chunk (2 chunks, double-buffered)

__device__ __forceinline__ void cp_async16(unsigned smem_addr, const void* gptr) {
    asm volatile("cp.async.cg.shared.global [%0], [%1], 16;\n"
                 :: "r"(smem_addr), "l"(gptr));
}
__device__ __forceinline__ void cp_commit() {
    asm volatile("cp.async.commit_group;\n");
}
template <int N>
__device__ __forceinline__ void cp_wait() {
    asm volatile("cp.async.wait_group %0;\n" :: "n"(N));
}

__global__ __launch_bounds__(128)
void disp_corr_kernel(const float* __restrict__ x, float* __restrict__ out) {
    __shared__ float Lsh[2][CH][TW];   // 2 x 8 KB
    __shared__ float Rsh[2][CH][RW];   // 2 x 12 KB

    const int tile = blockIdx.x;            // 0..3
    const int h    = blockIdx.y;            // 0..255
    const int b    = blockIdx.z;            // 0..3
    const int tile_start = tile * TW;
    const int tid = threadIdx.x;

    const size_t chan_stride = (size_t)HH * WW;

    const float* Lg = x + ((size_t)(b * 2 * CC) * HH + h) * WW + tile_start;
    const float* Rg = x + ((size_t)(b * 2 * CC + CC) * HH + h) * WW;

    // ---- async chunk loader: chunk ck (channels [ck*CH, ck*CH+CH)) -> buffer ck ----
    auto load_chunk = [&](int ck) {
        const int c0 = ck * CH;
        // L: CH*TW/4 = 512 float4, 4 per thread
        #pragma unroll
        for (int k = 0; k < (CH * TW / 4) / 128; k++) {
            int idx = k * 128 + tid;
            int c  = idx / (TW / 4);
            int w4 = idx % (TW / 4);
            unsigned sa = (unsigned)__cvta_generic_to_shared(&Lsh[ck][c][4 * w4]);
            cp_async16(sa, Lg + (size_t)(c0 + c) * chan_stride + 4 * w4);
        }
        // R: CH*RW/4 = 768 float4, 6 per thread
        #pragma unroll
        for (int k = 0; k < (CH * (RW / 4)) / 128; k++) {
            int idx = k * 128 + tid;
            int c  = idx / (RW / 4);
            int j4 = idx % (RW / 4);
            int wg = tile_start + 4 * j4 - 64;
            if (wg >= 0) {
                unsigned sa = (unsigned)__cvta_generic_to_shared(&Rsh[ck][c][4 * j4]);
                cp_async16(sa, Rg + (size_t)(c0 + c) * chan_stride + wg);
            } else {
                *(float4*)&Rsh[ck][c][4 * j4] = make_float4(0.f, 0.f, 0.f, 0.f);
            }
        }
        cp_commit();
    };

    load_chunk(0);   // group 0 in flight

    const int lane = tid & 31;
    const int warp = tid >> 5;            // 0..3
    const int w0 = lane * 4;              // stride-16B across lanes: conflict-free LDS.128
    const int d0 = warp * ND;             // 0,16,32,48

    float acc[ND][NW];
    #pragma unroll
    for (int i = 0; i < ND; i++)
        #pragma unroll
        for (int j = 0; j < NW; j++) acc[i][j] = 0.f;

    // R shared index for (w0+i, d0+dd) is 64 + w0 + i - d0 - dd = rbase + 16 - dd + i
    const int rbase = 64 + w0 - d0 - 16;   // multiple of 4

    auto compute_chunk = [&](int ck) {
        #pragma unroll 2
        for (int c = 0; c < CH; c++) {
            float4 Lv = *(const float4*)&Lsh[ck][c][w0];

            float r[20];
            #pragma unroll
            for (int q = 0; q < 5; q++)
                *(float4*)&r[4 * q] = *(const float4*)&Rsh[ck][c][rbase + 4 * q];

            #pragma unroll
            for (int dd = 0; dd < ND; dd++) {
                acc[dd][0] = fmaf(Lv.x, r[16 - dd + 0], acc[dd][0]);
                acc[dd][1] = fmaf(Lv.y, r[16 - dd + 1], acc[dd][1]);
                acc[dd][2] = fmaf(Lv.z, r[16 - dd + 2], acc[dd][2]);
                acc[dd][3] = fmaf(Lv.w, r[16 - dd + 3], acc[dd][3]);
            }
        }
    };

    // Pipeline: start chunk 1 loads, then compute chunk 0 (hides DRAM latency), then chunk 1.
    load_chunk(1);   // group 1 in flight
    cp_wait<1>();    // chunk 0 landed
    __syncthreads();
    compute_chunk(0);
    cp_wait<0>();    // chunk 1 landed
    __syncthreads();
    compute_chunk(1);

    // ---- Epilogue: scale by 1/C and store (float4, contiguous per warp) ----
    const float inv_c = 1.0f / (float)CC;
    float* og = out + (((size_t)b * DD + d0) * HH + h) * WW + tile_start + w0;
    #pragma unroll
    for (int dd = 0; dd < ND; dd++) {
        float4 v = make_float4(acc[dd][0] * inv_c, acc[dd][1] * inv_c,
                               acc[dd][2] * inv_c, acc[dd][3] * inv_c);
        *(float4*)(og + (size_t)dd * chan_stride) = v;
    }
}

extern "C" void kernel_launch(void* const* d_in, const int* in_sizes, int n_in,
                              void* d_out, int out_size) {
    const float* x = (const float*)d_in[0];
    float* out = (float*)d_out;
    dim3 grid(WW / TW, HH, BB);   // (4, 256, 4) = 4096 blocks
    disp_corr_kernel<<<grid, 128>>>(x, out);
}